// round 10
// baseline (speedup 1.0000x reference)
#include <cuda_runtime.h>
#include <cuda_bf16.h>
#include <cuda_fp16.h>
#include <cstdint>

#define SEQ   8192
#define DIN   768
#define DOUT  128
#define KSPLIT 4096
#define NIT   (KSPLIT / 128)   // 32

// ---------------------------------------------------------------------------
// Device-global scratch
// ---------------------------------------------------------------------------
__device__ __align__(16) __half g_xh[SEQ * DIN], g_xl[SEQ * DIN];
__device__ __align__(16) __half g_wh[3 * DOUT * DIN];
__device__ __align__(16) __half g_qh[SEQ * DOUT], g_ql[SEQ * DOUT];
__device__ __align__(16) __half g_kh[SEQ * DOUT];
__device__ __align__(16) __half g_vt[DOUT * SEQ];   // V^T [d][seq]
__device__ float g_po[2 * SEQ * DOUT];              // unnormalized O partials
__device__ float g_pl[2 * SEQ];                     // row-sum partials

// ---------------------------------------------------------------------------
// Helpers
// ---------------------------------------------------------------------------
__device__ __forceinline__ uint32_t smem_u32(const void* p) {
    uint32_t a;
    asm("{ .reg .u64 t; cvta.to.shared.u64 t, %1; cvt.u32.u64 %0, t; }"
        : "=r"(a) : "l"(p));
    return a;
}
__device__ __forceinline__ float ex2f(float x) {
    float y; asm("ex2.approx.f32 %0, %1;" : "=f"(y) : "f"(x)); return y;
}
__device__ __forceinline__ uint32_t packh2(__half a, __half b) {
    __half2 t = __halves2half2(a, b);
    return *(uint32_t*)&t;
}
__device__ __forceinline__ uint32_t packh2f(float a, float b) {
    __half2 t = __floats2half2_rn(a, b);
    return *(uint32_t*)&t;
}
__device__ __forceinline__ void ldm_x4(uint32_t* r, uint32_t addr) {
    asm volatile("ldmatrix.sync.aligned.m8n8.x4.shared.b16 {%0,%1,%2,%3}, [%4];"
        : "=r"(r[0]), "=r"(r[1]), "=r"(r[2]), "=r"(r[3]) : "r"(addr));
}
__device__ __forceinline__ void mma_f16(float* c, const uint32_t* a,
                                        const uint32_t* b) {
    asm volatile("mma.sync.aligned.m16n8k16.row.col.f32.f16.f16.f32 "
        "{%0,%1,%2,%3}, {%4,%5,%6,%7}, {%8,%9}, {%0,%1,%2,%3};"
        : "+f"(c[0]), "+f"(c[1]), "+f"(c[2]), "+f"(c[3])
        : "r"(a[0]), "r"(a[1]), "r"(a[2]), "r"(a[3]), "r"(b[0]), "r"(b[1]));
}
__device__ __forceinline__ void cpa16(uint32_t dst, const void* src) {
    asm volatile("cp.async.cg.shared.global [%0], [%1], 16;"
                 :: "r"(dst), "l"(src));
}
#define CP_COMMIT() asm volatile("cp.async.commit_group;" ::: "memory")
#define CP_WAIT(n)  asm volatile("cp.async.wait_group %0;" :: "n"(n) : "memory")

// ---------------------------------------------------------------------------
// Kernel 0: streaming fp32 -> fp16 conversion.
// Blocks [0,3072): x -> xh (hi) + xl (residual). Blocks [3072,3216): w -> wh.
// Each thread converts 8 floats.
// ---------------------------------------------------------------------------
__global__ __launch_bounds__(256) void convert_kernel(
    const float* __restrict__ x,
    const float* __restrict__ wq,
    const float* __restrict__ wk,
    const float* __restrict__ wv)
{
    const int b = blockIdx.x;
    const int tid = threadIdx.x;
    if (b < 3072) {
        size_t base = (size_t)b * 2048 + tid * 8;
        float4 f0 = *(const float4*)(x + base);
        float4 f1 = *(const float4*)(x + base + 4);
        __half h0 = __float2half_rn(f0.x), h1 = __float2half_rn(f0.y),
               h2 = __float2half_rn(f0.z), h3 = __float2half_rn(f0.w),
               h4 = __float2half_rn(f1.x), h5 = __float2half_rn(f1.y),
               h6 = __float2half_rn(f1.z), h7 = __float2half_rn(f1.w);
        *(uint4*)(g_xh + base) = make_uint4(
            packh2(h0, h1), packh2(h2, h3), packh2(h4, h5), packh2(h6, h7));
        *(uint4*)(g_xl + base) = make_uint4(
            packh2f(f0.x - __half2float(h0), f0.y - __half2float(h1)),
            packh2f(f0.z - __half2float(h2), f0.w - __half2float(h3)),
            packh2f(f1.x - __half2float(h4), f1.y - __half2float(h5)),
            packh2f(f1.z - __half2float(h6), f1.w - __half2float(h7)));
    } else {
        int wb = b - 3072;                     // 0..143 (48 per matrix)
        const float* w = (wb < 48) ? wq : (wb < 96) ? wk : wv;
        int mi = wb / 48;
        size_t off = (size_t)(wb % 48) * 2048 + tid * 8;
        float4 f0 = *(const float4*)(w + off);
        float4 f1 = *(const float4*)(w + off + 4);
        *(uint4*)(g_wh + (size_t)mi * DOUT * DIN + off) = make_uint4(
            packh2f(f0.x, f0.y), packh2f(f0.z, f0.w),
            packh2f(f1.x, f1.y), packh2f(f1.z, f1.w));
    }
}

// ---------------------------------------------------------------------------
// Kernel 1: QKV projection, pure fp16 pipelined GEMM (2-term x hi/lo vs w hi).
// BM=128, BN=128, K-stages of 64, cp.async double-buffered.
// 8 warps: 4m x 2n (warp 32x64). Stage rows: 64 halves = 8 chunks of 16B.
// ---------------------------------------------------------------------------
#define QSTG  49152                 // bytes per stage (xh 16K + xl 16K + wh 16K)
#define QSXH(s) ((s) * QSTG + 0)
#define QSXL(s) ((s) * QSTG + 16384)
#define QSWH(s) ((s) * QSTG + 32768)
#define QSMEM (2 * QSTG)

__global__ __launch_bounds__(256) void qkv_kernel()
{
    extern __shared__ char sm[];
    const uint32_t smb = smem_u32(sm);
    const int tid  = threadIdx.x;
    const int lane = tid & 31;
    const int wid  = tid >> 5;
    const int wm   = wid & 3;
    const int wn   = wid >> 2;
    const int g    = lane >> 2;
    const int q    = lane & 3;
    const int rr   = lane & 7;
    const int am   = lane >> 3;
    const int arow_off = rr + ((am & 1) << 3);
    const int achunk   = am >> 1;
    const int l4   = lane >> 3;
    const int bn_off   = ((l4 >> 1) << 3) + rr;
    const int bk_half  = l4 & 1;
    const int m0 = blockIdx.x * 128;
    const int by = blockIdx.y;
    const __half* wsrc = g_wh + (size_t)by * DOUT * DIN;

    // async-load one stage (xh, xl, wh tiles of 128x64 halves)
    auto load_stage = [&](int s, int k0) {
        uint32_t xh = smb + QSXH(s), xl = smb + QSXL(s), wh = smb + QSWH(s);
#pragma unroll
        for (int u = 0; u < 4; u++) {
            int idx = tid + 256 * u;          // 1024 = 128 rows x 8 chunks
            int r = idx >> 3, ch = idx & 7;
            uint32_t dst = (r << 7) + ((ch ^ (r & 7)) << 4);
            cpa16(xh + dst, g_xh + (size_t)(m0 + r) * DIN + k0 + ch * 8);
            cpa16(xl + dst, g_xl + (size_t)(m0 + r) * DIN + k0 + ch * 8);
            cpa16(wh + dst, wsrc + (size_t)r * DIN + k0 + ch * 8);
        }
    };

    float c[2][8][4];
#pragma unroll
    for (int mt = 0; mt < 2; mt++)
#pragma unroll
        for (int nt = 0; nt < 8; nt++)
#pragma unroll
            for (int v = 0; v < 4; v++) c[mt][nt][v] = 0.0f;

    load_stage(0, 0);
    CP_COMMIT();

    for (int st = 0; st < DIN / 64; st++) {
        const int s = st & 1;
        if (st > 0) __syncthreads();          // stage s fully consumed before reuse
        if (st + 1 < DIN / 64) load_stage(s ^ 1, (st + 1) * 64);
        CP_COMMIT();                          // (possibly empty) group
        CP_WAIT(1);                           // current stage resident
        __syncthreads();

#pragma unroll
        for (int ks = 0; ks < 4; ks++) {
            uint32_t ah[2][4], al[2][4];
#pragma unroll
            for (int mt = 0; mt < 2; mt++) {
                int ar = wm * 32 + mt * 16 + arow_off;
                int ch = 2 * ks + achunk;
                uint32_t aaddr = smb + QSXH(s) + (ar << 7) +
                                 ((ch ^ (ar & 7)) << 4);
                ldm_x4(ah[mt], aaddr);
                ldm_x4(al[mt], aaddr + 16384);
            }
#pragma unroll
            for (int ntp = 0; ntp < 4; ntp++) {
                int br = wn * 64 + ntp * 16 + bn_off;
                int ch = 2 * ks + bk_half;
                uint32_t baddr = smb + QSWH(s) + (br << 7) +
                                 ((ch ^ (br & 7)) << 4);
                uint32_t bh[4];
                ldm_x4(bh, baddr);
#pragma unroll
                for (int mt = 0; mt < 2; mt++) {
                    mma_f16(c[mt][2 * ntp],     ah[mt], bh);
                    mma_f16(c[mt][2 * ntp],     al[mt], bh);
                    mma_f16(c[mt][2 * ntp + 1], ah[mt], bh + 2);
                    mma_f16(c[mt][2 * ntp + 1], al[mt], bh + 2);
                }
            }
        }
    }

    // ---- epilogue ----
    if (by == 0) {
        const float factor = 0.08838834764831845f * 1.4426950408889634f;
#pragma unroll
        for (int mt = 0; mt < 2; mt++) {
            int r1 = m0 + wm * 32 + mt * 16 + g;
            int r2 = r1 + 8;
#pragma unroll
            for (int nt = 0; nt < 8; nt++) {
                int col = wn * 64 + nt * 8 + 2 * q;
                float v0 = c[mt][nt][0] * factor, v1 = c[mt][nt][1] * factor;
                float v2 = c[mt][nt][2] * factor, v3 = c[mt][nt][3] * factor;
                __half a0 = __float2half_rn(v0), a1 = __float2half_rn(v1);
                __half a2 = __float2half_rn(v2), a3 = __float2half_rn(v3);
                *(uint32_t*)(g_qh + (size_t)r1 * DOUT + col) = packh2(a0, a1);
                *(uint32_t*)(g_qh + (size_t)r2 * DOUT + col) = packh2(a2, a3);
                *(uint32_t*)(g_ql + (size_t)r1 * DOUT + col) =
                    packh2f(v0 - __half2float(a0), v1 - __half2float(a1));
                *(uint32_t*)(g_ql + (size_t)r2 * DOUT + col) =
                    packh2f(v2 - __half2float(a2), v3 - __half2float(a3));
            }
        }
    } else if (by == 1) {
#pragma unroll
        for (int mt = 0; mt < 2; mt++) {
            int r1 = m0 + wm * 32 + mt * 16 + g;
            int r2 = r1 + 8;
#pragma unroll
            for (int nt = 0; nt < 8; nt++) {
                int col = wn * 64 + nt * 8 + 2 * q;
                *(uint32_t*)(g_kh + (size_t)r1 * DOUT + col) =
                    packh2f(c[mt][nt][0], c[mt][nt][1]);
                *(uint32_t*)(g_kh + (size_t)r2 * DOUT + col) =
                    packh2f(c[mt][nt][2], c[mt][nt][3]);
            }
        }
    } else {
        __half* stg = (__half*)sm;     // [128 d][132]
        __syncthreads();
#pragma unroll
        for (int mt = 0; mt < 2; mt++) {
            int r1 = wm * 32 + mt * 16 + g;
            int r2 = r1 + 8;
#pragma unroll
            for (int nt = 0; nt < 8; nt++) {
                int col = wn * 64 + nt * 8 + 2 * q;
                stg[(col)     * 132 + r1] = __float2half_rn(c[mt][nt][0]);
                stg[(col + 1) * 132 + r1] = __float2half_rn(c[mt][nt][1]);
                stg[(col)     * 132 + r2] = __float2half_rn(c[mt][nt][2]);
                stg[(col + 1) * 132 + r2] = __float2half_rn(c[mt][nt][3]);
            }
        }
        __syncthreads();
        int d  = tid >> 1;
        int r0 = (tid & 1) * 64;
#pragma unroll
        for (int u = 0; u < 8; u++) {
            int rb = r0 + u * 8;
            const __half* s = stg + d * 132 + rb;
            *(uint4*)(g_vt + (size_t)d * SEQ + m0 + rb) = make_uint4(
                packh2(s[0], s[1]), packh2(s[2], s[3]),
                packh2(s[4], s[5]), packh2(s[6], s[7]));
        }
    }
}

// ---------------------------------------------------------------------------
// Kernel 2: flash attention (unchanged from R8). BM=128, 8 warps = 4m x 2n,
// register-resident P, 2-way KV split, epilogue n-warp reduction.
// ---------------------------------------------------------------------------
#define OFF_QH  0
#define OFF_QL  32768
#define OFF_K0  65536          // + s*32768
#define OFF_V0  131072         // + s*32768
#define OFF_OX  65536          // epilogue O exchange (aliases K stages)
#define OFF_LS  196608
#define FSMEM   (196608 + 1024)

__global__ __launch_bounds__(256, 1) void flash_kernel()
{
    extern __shared__ char sm[];
    const uint32_t smb = smem_u32(sm);
    const int tid  = threadIdx.x;
    const int lane = tid & 31;
    const int wid  = tid >> 5;
    const int wm   = wid & 3;        // 4 m-warps (32 rows each)
    const int wn   = wid >> 2;       // 2 key-half warps (64 keys each)
    const int g    = lane >> 2;
    const int q    = lane & 3;
    const int rr   = lane & 7;
    const int am   = lane >> 3;
    const int arow_off = rr + ((am & 1) << 3);
    const int achunk   = am >> 1;
    const int l4   = lane >> 3;
    const int bn_off   = ((l4 >> 1) << 3) + rr;
    const int bk_half  = l4 & 1;
    const int q0   = blockIdx.x * 128;
    const int kb0  = blockIdx.y * KSPLIT;

    // ---- prologue: async Q (hi/lo), K(0), V(0) ----
#pragma unroll
    for (int u = 0; u < 8; u++) {
        int idx = tid + 256 * u;       // 2048 = 128 rows x 16 chunks
        int r = idx >> 4, ch = idx & 15;
        uint32_t off = (r << 8) + ((ch ^ (r & 7)) << 4);
        cpa16(smb + OFF_QH + off, g_qh + (size_t)(q0 + r) * DOUT + ch * 8);
        cpa16(smb + OFF_QL + off, g_ql + (size_t)(q0 + r) * DOUT + ch * 8);
        cpa16(smb + OFF_K0 + off, g_kh + (size_t)(kb0 + r) * DOUT + ch * 8);
        cpa16(smb + OFF_V0 + off, g_vt + (size_t)r * SEQ + kb0 + ch * 8);
    }
    CP_COMMIT();

    float o[2][16][4];
    float la[4];
#pragma unroll
    for (int mt = 0; mt < 2; mt++)
#pragma unroll
        for (int nd = 0; nd < 16; nd++)
#pragma unroll
            for (int v = 0; v < 4; v++) o[mt][nd][v] = 0.0f;
    la[0] = la[1] = la[2] = la[3] = 0.0f;

    CP_WAIT(0);
    __syncthreads();

    for (int it = 0; it < NIT; it++) {
        const int s = it & 1;

        if (it + 1 < NIT) {
            const int kb2 = kb0 + (it + 1) * 128;
            uint32_t kdst = smb + OFF_K0 + (s ^ 1) * 32768;
            uint32_t vdst = smb + OFF_V0 + (s ^ 1) * 32768;
#pragma unroll
            for (int u = 0; u < 8; u++) {
                int idx = tid + 256 * u;
                int r = idx >> 4, ch = idx & 15;
                uint32_t off = (r << 8) + ((ch ^ (r & 7)) << 4);
                cpa16(kdst + off, g_kh + (size_t)(kb2 + r) * DOUT + ch * 8);
                cpa16(vdst + off, g_vt + (size_t)r * SEQ + kb2 + ch * 8);
            }
        }
        CP_COMMIT();

        const uint32_t kbase = smb + OFF_K0 + s * 32768;
        const uint32_t vbase = smb + OFF_V0 + s * 32768;

        // ---- S = Q' K^T : warp = 32 rows x 64 keys, 2-term fp16 ----
        float sc[2][8][4];
#pragma unroll
        for (int mt = 0; mt < 2; mt++)
#pragma unroll
            for (int nt = 0; nt < 8; nt++)
#pragma unroll
                for (int v = 0; v < 4; v++) sc[mt][nt][v] = 0.0f;

#pragma unroll
        for (int kc = 0; kc < 8; kc++) {
            uint32_t ah[2][4], al[2][4];
#pragma unroll
            for (int mt = 0; mt < 2; mt++) {
                int ar = wm * 32 + mt * 16 + arow_off;
                uint32_t aaddr = smb + OFF_QH + (ar << 8) +
                                 (((2 * kc + achunk) ^ (ar & 7)) << 4);
                ldm_x4(ah[mt], aaddr);
                ldm_x4(al[mt], aaddr + 32768);
            }
#pragma unroll
            for (int kg = 0; kg < 4; kg++) {
                int br = wn * 64 + kg * 16 + bn_off;
                uint32_t baddr = kbase + (br << 8) +
                                 (((2 * kc + bk_half) ^ (br & 7)) << 4);
                uint32_t bh[4];
                ldm_x4(bh, baddr);
#pragma unroll
                for (int mt = 0; mt < 2; mt++) {
                    mma_f16(sc[mt][2 * kg],     ah[mt], bh);
                    mma_f16(sc[mt][2 * kg],     al[mt], bh);
                    mma_f16(sc[mt][2 * kg + 1], ah[mt], bh + 2);
                    mma_f16(sc[mt][2 * kg + 1], al[mt], bh + 2);
                }
            }
        }

        // ---- softmax in registers ----
        uint32_t pa[2][4][4];
#pragma unroll
        for (int mt = 0; mt < 2; mt++)
#pragma unroll
            for (int kck = 0; kck < 4; kck++) {
                float e0 = ex2f(sc[mt][2 * kck][0]);
                float e1 = ex2f(sc[mt][2 * kck][1]);
                float e2 = ex2f(sc[mt][2 * kck][2]);
                float e3 = ex2f(sc[mt][2 * kck][3]);
                float f0 = ex2f(sc[mt][2 * kck + 1][0]);
                float f1 = ex2f(sc[mt][2 * kck + 1][1]);
                float f2 = ex2f(sc[mt][2 * kck + 1][2]);
                float f3 = ex2f(sc[mt][2 * kck + 1][3]);
                la[mt * 2 + 0] += (e0 + e1) + (f0 + f1);
                la[mt * 2 + 1] += (e2 + e3) + (f2 + f3);
                pa[mt][kck][0] = packh2f(e0, e1);
                pa[mt][kck][1] = packh2f(e2, e3);
                pa[mt][kck][2] = packh2f(f0, f1);
                pa[mt][kck][3] = packh2f(f2, f3);
            }

        // ---- O += P V ----
#pragma unroll
        for (int kck = 0; kck < 4; kck++) {
            const int chv = wn * 8 + 2 * kck + bk_half;
#pragma unroll
            for (int dg = 0; dg < 8; dg++) {
                int br = dg * 16 + bn_off;
                uint32_t baddr = vbase + (br << 8) + ((chv ^ (br & 7)) << 4);
                uint32_t bv[4];
                ldm_x4(bv, baddr);
#pragma unroll
                for (int mt = 0; mt < 2; mt++) {
                    mma_f16(o[mt][2 * dg],     pa[mt][kck], bv);
                    mma_f16(o[mt][2 * dg + 1], pa[mt][kck], bv + 2);
                }
            }
        }

        if (it + 1 < NIT) {
            CP_WAIT(0);
            __syncthreads();
        }
    }

    // ---- epilogue: sum n-warp partials, emit unnormalized O + l ----
#pragma unroll
    for (int v = 0; v < 4; v++) {
        la[v] += __shfl_xor_sync(0xffffffffu, la[v], 1);
        la[v] += __shfl_xor_sync(0xffffffffu, la[v], 2);
    }
    __syncthreads();   // all MMAs done before OX overwrites K stages

    float* lbuf = (float*)(sm + OFF_LS);   // [2 wn][128 rows]
    if (q == 0) {
#pragma unroll
        for (int mt = 0; mt < 2; mt++)
#pragma unroll
            for (int h = 0; h < 2; h++)
                lbuf[wn * 128 + wm * 32 + mt * 16 + h * 8 + g] = la[mt * 2 + h];
    }
    if (wn == 1) {
        char* ox = sm + OFF_OX + wm * 16384;
#pragma unroll
        for (int mt = 0; mt < 2; mt++) {
            int r1 = mt * 16 + g;
#pragma unroll
            for (int nd = 0; nd < 16; nd++) {
                int col = nd * 8 + 2 * q;
                *(float2*)(ox + r1 * 512 + col * 4) =
                    make_float2(o[mt][nd][0], o[mt][nd][1]);
                *(float2*)(ox + (r1 + 8) * 512 + col * 4) =
                    make_float2(o[mt][nd][2], o[mt][nd][3]);
            }
        }
    }
    __syncthreads();
    if (wn == 0) {
        const char* ox = sm + OFF_OX + wm * 16384;
        const size_t obase = (size_t)blockIdx.y * SEQ + q0;
#pragma unroll
        for (int mt = 0; mt < 2; mt++) {
            int r1 = mt * 16 + g;
            int row1 = wm * 32 + r1;
#pragma unroll
            for (int nd = 0; nd < 16; nd++) {
                int col = nd * 8 + 2 * q;
                float2 a1 = *(const float2*)(ox + r1 * 512 + col * 4);
                float2 a2 = *(const float2*)(ox + (r1 + 8) * 512 + col * 4);
                *(float2*)(g_po + (obase + row1) * DOUT + col) =
                    make_float2(o[mt][nd][0] + a1.x, o[mt][nd][1] + a1.y);
                *(float2*)(g_po + (obase + row1 + 8) * DOUT + col) =
                    make_float2(o[mt][nd][2] + a2.x, o[mt][nd][3] + a2.y);
            }
            if (q == 0) {
#pragma unroll
                for (int h = 0; h < 2; h++) {
                    int row = wm * 32 + mt * 16 + h * 8 + g;
                    g_pl[obase + row] = lbuf[row] + lbuf[128 + row];
                }
            }
        }
    }
}

// ---------------------------------------------------------------------------
// Kernel 3: combine the 2 KV-split partials
// ---------------------------------------------------------------------------
__global__ __launch_bounds__(256) void combine_kernel(float* __restrict__ out)
{
    int i = blockIdx.x * 256 + threadIdx.x;
    int r = i >> 7;
    float v = g_po[i] + g_po[SEQ * DOUT + i];
    float l = g_pl[r] + g_pl[SEQ + r];
    out[i] = v / l;
}

extern "C" void kernel_launch(void* const* d_in, const int* in_sizes, int n_in,
                              void* d_out, int out_size)
{
    (void)in_sizes; (void)n_in; (void)out_size;
    const float* x  = (const float*)d_in[0];
    const float* wq = (const float*)d_in[1];
    const float* wk = (const float*)d_in[2];
    const float* wv = (const float*)d_in[3];
    float* out = (float*)d_out;

    cudaFuncSetAttribute(qkv_kernel,
                         cudaFuncAttributeMaxDynamicSharedMemorySize, QSMEM);
    cudaFuncSetAttribute(flash_kernel,
                         cudaFuncAttributeMaxDynamicSharedMemorySize, FSMEM);

    convert_kernel<<<3072 + 144, 256>>>(x, wq, wk, wv);
    qkv_kernel<<<dim3(SEQ / 128, 3), 256, QSMEM>>>();
    flash_kernel<<<dim3(SEQ / 128, 2), 256, FSMEM>>>();
    combine_kernel<<<(SEQ * DOUT) / 256, 256>>>(out);
}